// round 1
// baseline (speedup 1.0000x reference)
#include <cuda_runtime.h>
#include <math.h>

#define MTOK 4096      // B*S tokens
#define DMOD 1024
#define SEQ  2048
#define NH   16
#define DK   64

// scratch (no cudaMalloc allowed)
__device__ float g_q[MTOK * DMOD];
__device__ float g_k[MTOK * DMOD];
__device__ float g_v[MTOK * DMOD];
__device__ float g_o[MTOK * DMOD];

// ---------------------------------------------------------------------------
// C[m][n] = sum_k A[m][k] * W[n][k]   (A: MxK, W: NxK, C: MxN, row-major)
// 128x128 tile, BK=16, 256 threads, 8x8 microtile (split 4+4 halves).
// ---------------------------------------------------------------------------
__global__ __launch_bounds__(256) void sgemm_nt(const float* __restrict__ A,
                                                const float* __restrict__ W,
                                                float* __restrict__ C,
                                                int M, int N, int K)
{
    __shared__ float As[16][132];   // [k][m], +4 pad kills transpose-store conflicts
    __shared__ float Ws[16][132];   // [k][n]

    const int tid = threadIdx.x;
    const int m0 = blockIdx.y * 128;
    const int n0 = blockIdx.x * 128;
    const int tyy = tid >> 4;       // 0..15 -> row fragment
    const int txx = tid & 15;       // 0..15 -> col fragment

    float acc[8][8];
#pragma unroll
    for (int i = 0; i < 8; i++)
#pragma unroll
        for (int j = 0; j < 8; j++) acc[i][j] = 0.f;

    for (int k0 = 0; k0 < K; k0 += 16) {
        __syncthreads();
#pragma unroll
        for (int it = 0; it < 2; it++) {
            int idx = it * 256 + tid;       // 0..511 float4 slots (128 rows x 4)
            int r   = idx >> 2;
            int f4  = idx & 3;
            float4 va = *(const float4*)(A + (size_t)(m0 + r) * K + k0 + f4 * 4);
            As[f4 * 4 + 0][r] = va.x; As[f4 * 4 + 1][r] = va.y;
            As[f4 * 4 + 2][r] = va.z; As[f4 * 4 + 3][r] = va.w;
            float4 vw = *(const float4*)(W + (size_t)(n0 + r) * K + k0 + f4 * 4);
            Ws[f4 * 4 + 0][r] = vw.x; Ws[f4 * 4 + 1][r] = vw.y;
            Ws[f4 * 4 + 2][r] = vw.z; Ws[f4 * 4 + 3][r] = vw.w;
        }
        __syncthreads();
#pragma unroll
        for (int kk = 0; kk < 16; kk++) {
            float ra[8], rb[8];
            *(float4*)&ra[0] = *(const float4*)&As[kk][tyy * 4];
            *(float4*)&ra[4] = *(const float4*)&As[kk][64 + tyy * 4];
            *(float4*)&rb[0] = *(const float4*)&Ws[kk][txx * 4];
            *(float4*)&rb[4] = *(const float4*)&Ws[kk][64 + txx * 4];
#pragma unroll
            for (int i = 0; i < 8; i++)
#pragma unroll
                for (int j = 0; j < 8; j++)
                    acc[i][j] += ra[i] * rb[j];
        }
    }

#pragma unroll
    for (int ih = 0; ih < 2; ih++) {
#pragma unroll
        for (int i = 0; i < 4; i++) {
            int row = m0 + ih * 64 + tyy * 4 + i;
            float* crow = C + (size_t)row * N + n0;
            float4 v0 = make_float4(acc[ih * 4 + i][0], acc[ih * 4 + i][1],
                                    acc[ih * 4 + i][2], acc[ih * 4 + i][3]);
            float4 v1 = make_float4(acc[ih * 4 + i][4], acc[ih * 4 + i][5],
                                    acc[ih * 4 + i][6], acc[ih * 4 + i][7]);
            *(float4*)(crow + txx * 4)      = v0;
            *(float4*)(crow + 64 + txx * 4) = v1;
        }
    }
}

// ---------------------------------------------------------------------------
// RoPE in-place on Q and K. One thread per (token, head, pair).
// Matches the reference numerically: freq/angle in f32, but range-reduce the
// angle in double before sin/cos so fast-math trig can't blow up at |x|~2048.
// ---------------------------------------------------------------------------
__global__ void rope_kernel(float* __restrict__ q, float* __restrict__ k,
                            const int* __restrict__ pos)
{
    int idx = blockIdx.x * blockDim.x + threadIdx.x;   // MTOK*512 pairs
    if (idx >= MTOK * 512) return;
    int m   = idx >> 9;
    int rem = idx & 511;
    int h   = rem >> 5;
    int i   = rem & 31;

    int p = pos[m];
    float freq = (float)exp(-((double)(2 * i) / 64.0) * 9.210340371976184); // ln(1e4)
    float ang  = (float)p * freq;
    double angd = (double)ang;
    const double twopi = 6.283185307179586476925287;
    angd -= floor(angd / twopi) * twopi;
    float ar = (float)angd;
    float c = cosf(ar), s = sinf(ar);

    size_t off = (size_t)m * DMOD + h * DK + 2 * i;
    float qe = q[off], qo = q[off + 1];
    q[off]     = qe * c - qo * s;
    q[off + 1] = qe * s + qo * c;
    float ke = k[off], ko = k[off + 1];
    k[off]     = ke * c - ko * s;
    k[off + 1] = ke * s + ko * c;
}

// ---------------------------------------------------------------------------
// Flash attention, causal. One block = (q-tile of 64, head, batch).
// 256 threads as 16x16; each thread owns a 4x4 microtile.
// smem: Q natural [q][d], K transposed+swizzled [d][k], V natural [k][d]
// (K/V share a buffer), P natural [q][k]. 3 x 16KB = 48KB exactly.
// ---------------------------------------------------------------------------
__global__ __launch_bounds__(256) void attn_kernel(const float* __restrict__ Q,
                                                   const float* __restrict__ K,
                                                   const float* __restrict__ V,
                                                   float* __restrict__ O)
{
    __shared__ float Qs[64][64];
    __shared__ float KVs[64][64];
    __shared__ float Ps[64][64];

    const int tid = threadIdx.x;
    const int ty = tid >> 4;     // 0..15 -> q rows ty*4..ty*4+3
    const int tx = tid & 15;     // 0..15 -> k/d cols tx*4..tx*4+3
    const int qt = blockIdx.x, h = blockIdx.y, b = blockIdx.z;
    const size_t base = ((size_t)b * SEQ) * DMOD + h * DK;

    // load Q tile (natural layout, coalesced)
#pragma unroll
    for (int it = 0; it < 4; it++) {
        int idx = it * 256 + tid;      // 1024 float4 slots
        int r = idx >> 4, f4 = idx & 15;
        *(float4*)&Qs[r][f4 * 4] =
            *(const float4*)(Q + base + (size_t)(qt * 64 + r) * DMOD + f4 * 4);
    }

    float m_run[4], l_run[4], acc[4][4];
#pragma unroll
    for (int i = 0; i < 4; i++) {
        m_run[i] = -1e30f; l_run[i] = 0.f;
#pragma unroll
        for (int j = 0; j < 4; j++) acc[i][j] = 0.f;
    }
    const float scale = 0.125f;   // 1/sqrt(64)

    for (int kt = 0; kt <= qt; kt++) {
        __syncthreads();           // prev PV reads of KVs done
        // K tile: store transposed [d][k] with XOR swizzle on k (keyed on d>>2)
#pragma unroll
        for (int it = 0; it < 4; it++) {
            int idx = it * 256 + tid;
            int s = idx >> 4, f4 = idx & 15;
            float4 v = *(const float4*)(K + base + (size_t)(kt * 64 + s) * DMOD + f4 * 4);
            int sw = s ^ ((f4 & 7) << 2);
            int d0 = f4 * 4;
            KVs[d0 + 0][sw] = v.x; KVs[d0 + 1][sw] = v.y;
            KVs[d0 + 2][sw] = v.z; KVs[d0 + 3][sw] = v.w;
        }
        __syncthreads();

        // S = Q K^T for this thread's 4x4
        float sreg[4][4];
#pragma unroll
        for (int i = 0; i < 4; i++)
#pragma unroll
            for (int j = 0; j < 4; j++) sreg[i][j] = 0.f;

#pragma unroll
        for (int d0 = 0; d0 < 64; d0 += 4) {
            float qa[4][4], kb[4][4];
            int colk = (tx * 4) ^ (((d0 >> 2) & 7) << 2);
#pragma unroll
            for (int i = 0; i < 4; i++)
                *(float4*)qa[i] = *(const float4*)&Qs[ty * 4 + i][d0];
#pragma unroll
            for (int c = 0; c < 4; c++)
                *(float4*)kb[c] = *(const float4*)&KVs[d0 + c][colk];
#pragma unroll
            for (int i = 0; i < 4; i++)
#pragma unroll
                for (int c = 0; c < 4; c++) {
                    float qv = qa[i][c];
#pragma unroll
                    for (int j = 0; j < 4; j++)
                        sreg[i][j] += qv * kb[c][j];
                }
        }

        // scale + causal mask (diagonal tile only)
        if (kt == qt) {
#pragma unroll
            for (int i = 0; i < 4; i++)
#pragma unroll
                for (int j = 0; j < 4; j++) {
                    sreg[i][j] *= scale;
                    if (tx * 4 + j > ty * 4 + i) sreg[i][j] = -1e30f;
                }
        } else {
#pragma unroll
            for (int i = 0; i < 4; i++)
#pragma unroll
                for (int j = 0; j < 4; j++) sreg[i][j] *= scale;
        }

        // online softmax; row reductions over the 16 tx lanes (xor 1,2,4,8)
#pragma unroll
        for (int i = 0; i < 4; i++) {
            float mx = fmaxf(fmaxf(sreg[i][0], sreg[i][1]),
                             fmaxf(sreg[i][2], sreg[i][3]));
#pragma unroll
            for (int off = 8; off >= 1; off >>= 1)
                mx = fmaxf(mx, __shfl_xor_sync(0xffffffffu, mx, off));
            float mnew  = fmaxf(m_run[i], mx);
            float alpha = __expf(m_run[i] - mnew);
            float rs = 0.f;
#pragma unroll
            for (int j = 0; j < 4; j++) {
                float p = __expf(sreg[i][j] - mnew);
                sreg[i][j] = p;
                rs += p;
            }
#pragma unroll
            for (int off = 8; off >= 1; off >>= 1)
                rs += __shfl_xor_sync(0xffffffffu, rs, off);
            l_run[i] = l_run[i] * alpha + rs;
            m_run[i] = mnew;
#pragma unroll
            for (int j = 0; j < 4; j++) acc[i][j] *= alpha;
        }

        // publish P
#pragma unroll
        for (int i = 0; i < 4; i++)
            *(float4*)&Ps[ty * 4 + i][tx * 4] =
                make_float4(sreg[i][0], sreg[i][1], sreg[i][2], sreg[i][3]);
        __syncthreads();           // P visible; K reads done -> reuse KVs for V

        // V tile (natural [k][d])
#pragma unroll
        for (int it = 0; it < 4; it++) {
            int idx = it * 256 + tid;
            int r = idx >> 4, f4 = idx & 15;
            *(float4*)&KVs[r][f4 * 4] =
                *(const float4*)(V + base + (size_t)(kt * 64 + r) * DMOD + f4 * 4);
        }
        __syncthreads();

        // O += P V
#pragma unroll
        for (int kk0 = 0; kk0 < 64; kk0 += 4) {
            float pa[4][4], vb[4][4];
#pragma unroll
            for (int i = 0; i < 4; i++)
                *(float4*)pa[i] = *(const float4*)&Ps[ty * 4 + i][kk0];
#pragma unroll
            for (int c = 0; c < 4; c++)
                *(float4*)vb[c] = *(const float4*)&KVs[kk0 + c][tx * 4];
#pragma unroll
            for (int i = 0; i < 4; i++)
#pragma unroll
                for (int c = 0; c < 4; c++) {
                    float pv = pa[i][c];
#pragma unroll
                    for (int j = 0; j < 4; j++)
                        acc[i][j] += pv * vb[c][j];
                }
        }
    }

    // epilogue: normalize and store to [b, s, h*64+d] layout
#pragma unroll
    for (int i = 0; i < 4; i++) {
        float inv = 1.f / l_run[i];
        int row = qt * 64 + ty * 4 + i;
        float4 out = make_float4(acc[i][0] * inv, acc[i][1] * inv,
                                 acc[i][2] * inv, acc[i][3] * inv);
        *(float4*)(O + base + (size_t)row * DMOD + tx * 4) = out;
    }
}

// ---------------------------------------------------------------------------
extern "C" void kernel_launch(void* const* d_in, const int* in_sizes, int n_in,
                              void* d_out, int out_size)
{
    const float* x   = (const float*)d_in[0];
    const float* Wq  = (const float*)d_in[1];
    const float* Wk  = (const float*)d_in[2];
    const float* Wv  = (const float*)d_in[3];
    const float* Wo  = (const float*)d_in[4];
    const int*   pos = (const int*)d_in[5];
    float* out = (float*)d_out;

    float *q, *k, *v, *o;
    cudaGetSymbolAddress((void**)&q, g_q);
    cudaGetSymbolAddress((void**)&k, g_k);
    cudaGetSymbolAddress((void**)&v, g_v);
    cudaGetSymbolAddress((void**)&o, g_o);

    dim3 gblk(DMOD / 128, MTOK / 128);
    sgemm_nt<<<gblk, 256>>>(x, Wq, q, MTOK, DMOD, DMOD);
    sgemm_nt<<<gblk, 256>>>(x, Wk, k, MTOK, DMOD, DMOD);
    sgemm_nt<<<gblk, 256>>>(x, Wv, v, MTOK, DMOD, DMOD);
    rope_kernel<<<(MTOK * 512) / 256, 256>>>(q, k, pos);
    attn_kernel<<<dim3(SEQ / 64, NH, 2), 256>>>(q, k, v, o);
    sgemm_nt<<<gblk, 256>>>(o, Wo, out, MTOK, DMOD, DMOD);
}

// round 3
// speedup vs baseline: 1.9208x; 1.9208x over previous
#include <cuda_runtime.h>
#include <cuda_fp16.h>
#include <cstdint>
#include <math.h>

#define MTOK 4096      // B*S tokens
#define DMOD 1024
#define SEQ  2048
#define NH   16
#define DK   64

// ---------------- scratch (no cudaMalloc allowed) ----------------
__device__ float g_q[MTOK * DMOD];
__device__ float g_k[MTOK * DMOD];
__device__ float g_v[MTOK * DMOD];
__device__ float g_o[MTOK * DMOD];
__device__ __half g_xh[MTOK * DMOD];
__device__ __half g_oh[MTOK * DMOD];
__device__ __half g_wh[4 * DMOD * DMOD];
__device__ float2 g_rtab[SEQ * 32];

// ---------------------------------------------------------------------------
// fp32 -> fp16 convert (vectorized)
// ---------------------------------------------------------------------------
__global__ void cvt_f16(const float* __restrict__ in, __half* __restrict__ out,
                        int n4)
{
    int i = blockIdx.x * blockDim.x + threadIdx.x;
    if (i >= n4) return;
    float4 v = ((const float4*)in)[i];
    __half2 h0 = __floats2half2_rn(v.x, v.y);
    __half2 h1 = __floats2half2_rn(v.z, v.w);
    ((__half2*)out)[i * 2]     = h0;
    ((__half2*)out)[i * 2 + 1] = h1;
}

// ---------------------------------------------------------------------------
// fp16 HMMA GEMM: C[m][n] = sum_k A[m][k] * W[n][k]  (both K-major)
// 128x128 CTA tile, BK=32, cp.async double-buffer, 8 warps (4m x 2n),
// warp tile 32x64, mma.sync m16n8k16 f32.f16.f16.f32, ldmatrix fragments.
// smem row stride 40 halves (80B) -> ldmatrix conflict-free permutation.
// ---------------------------------------------------------------------------
#define BM 128
#define BN 128
#define BK 32
#define SA 40          // padded row stride in halves

__global__ __launch_bounds__(256, 2) void hgemm(
    const __half* __restrict__ A, const __half* __restrict__ B,
    float* __restrict__ C, int M, int N, int K)
{
    __shared__ __align__(16) __half As[2][BM * SA];
    __shared__ __align__(16) __half Bs[2][BN * SA];

    const int tid = threadIdx.x;
    const int wid = tid >> 5, lane = tid & 31;
    const int wm = wid & 3, wn = wid >> 2;          // warp grid 4x2
    const int m0 = blockIdx.y * BM, n0 = blockIdx.x * BN;
    const int gid = lane >> 2, tg = lane & 3;       // mma group / thread-in-group

    const int ldrow = tid >> 2;                      // 0..63 (x2 iters -> 128)
    const int ldseg = tid & 3;                       // 16B segment in 64B row-chunk

    float acc[2][8][4];
#pragma unroll
    for (int i = 0; i < 2; i++)
#pragma unroll
        for (int j = 0; j < 8; j++)
#pragma unroll
            for (int r = 0; r < 4; r++) acc[i][j][r] = 0.f;

    auto issue_chunk = [&](int c, int buf) {
        const __half* ga = A + (size_t)m0 * K + (size_t)c * BK;
        const __half* gb = B + (size_t)n0 * K + (size_t)c * BK;
#pragma unroll
        for (int it = 0; it < 2; it++) {
            int row = it * 64 + ldrow;
            uint32_t sa = (uint32_t)__cvta_generic_to_shared(
                &As[buf][row * SA + ldseg * 8]);
            uint32_t sb = (uint32_t)__cvta_generic_to_shared(
                &Bs[buf][row * SA + ldseg * 8]);
            const __half* pa = ga + (size_t)row * K + ldseg * 8;
            const __half* pb = gb + (size_t)row * K + ldseg * 8;
            asm volatile("cp.async.cg.shared.global [%0], [%1], 16;"
                         :: "r"(sa), "l"(pa));
            asm volatile("cp.async.cg.shared.global [%0], [%1], 16;"
                         :: "r"(sb), "l"(pb));
        }
        asm volatile("cp.async.commit_group;");
    };

    const int KC = K / BK;
    issue_chunk(0, 0);

    // precompute per-lane ldmatrix address offsets
    const int a_row = wm * 32 + (lane & 15);         // + tm*16
    const int a_col = (lane & 16) >> 1;              // 0 or 8
    const int b_row = (lane & 7) + ((lane & 16) >> 1); // + wn*64 + nj
    const int b_col = (lane & 8);                    // 0 or 8

    for (int c = 0; c < KC; c++) {
        int buf = c & 1;
        if (c + 1 < KC) {
            issue_chunk(c + 1, buf ^ 1);
            asm volatile("cp.async.wait_group 1;");
        } else {
            asm volatile("cp.async.wait_group 0;");
        }
        __syncthreads();

#pragma unroll
        for (int ks = 0; ks < BK; ks += 16) {
            // A fragments: 2 m-tiles
            uint32_t af[2][4];
#pragma unroll
            for (int tm = 0; tm < 2; tm++) {
                uint32_t addr = (uint32_t)__cvta_generic_to_shared(
                    &As[buf][(a_row + tm * 16) * SA + ks + a_col]);
                asm volatile(
                    "ldmatrix.sync.aligned.m8n8.x4.shared.b16 {%0,%1,%2,%3}, [%4];"
                    : "=r"(af[tm][0]), "=r"(af[tm][1]),
                      "=r"(af[tm][2]), "=r"(af[tm][3]) : "r"(addr));
            }
            // B fragments: 8 n-tiles, loaded 2 at a time (x4)
            uint32_t bf[8][2];
#pragma unroll
            for (int np = 0; np < 4; np++) {
                uint32_t addr = (uint32_t)__cvta_generic_to_shared(
                    &Bs[buf][(wn * 64 + np * 16 + b_row) * SA + ks + b_col]);
                asm volatile(
                    "ldmatrix.sync.aligned.m8n8.x4.shared.b16 {%0,%1,%2,%3}, [%4];"
                    : "=r"(bf[np * 2][0]), "=r"(bf[np * 2][1]),
                      "=r"(bf[np * 2 + 1][0]), "=r"(bf[np * 2 + 1][1])
                    : "r"(addr));
            }
#pragma unroll
            for (int tm = 0; tm < 2; tm++)
#pragma unroll
                for (int tn = 0; tn < 8; tn++) {
                    asm volatile(
                        "mma.sync.aligned.m16n8k16.row.col.f32.f16.f16.f32 "
                        "{%0,%1,%2,%3}, {%4,%5,%6,%7}, {%8,%9}, {%0,%1,%2,%3};"
                        : "+f"(acc[tm][tn][0]), "+f"(acc[tm][tn][1]),
                          "+f"(acc[tm][tn][2]), "+f"(acc[tm][tn][3])
                        : "r"(af[tm][0]), "r"(af[tm][1]),
                          "r"(af[tm][2]), "r"(af[tm][3]),
                          "r"(bf[tn][0]), "r"(bf[tn][1]));
                }
        }
        __syncthreads();
    }

    // epilogue: direct fp32 stores (float2 per fragment row)
#pragma unroll
    for (int tm = 0; tm < 2; tm++) {
        int rbase = m0 + wm * 32 + tm * 16;
#pragma unroll
        for (int tn = 0; tn < 8; tn++) {
            int col = n0 + wn * 64 + tn * 8 + tg * 2;
            float* p0 = C + (size_t)(rbase + gid) * N + col;
            float* p1 = C + (size_t)(rbase + gid + 8) * N + col;
            *(float2*)p0 = make_float2(acc[tm][tn][0], acc[tm][tn][1]);
            *(float2*)p1 = make_float2(acc[tm][tn][2], acc[tm][tn][3]);
        }
    }
}

// ---------------------------------------------------------------------------
// RoPE: accurate table (FP64 once per (pos,i)), then memory-bound apply
// ---------------------------------------------------------------------------
__global__ void rope_table()
{
    int idx = blockIdx.x * blockDim.x + threadIdx.x;
    if (idx >= SEQ * 32) return;
    int p = idx >> 5, i = idx & 31;
    float freq = (float)exp(-((double)(2 * i) / 64.0) * 9.210340371976184); // ln(1e4)
    float ang  = (float)p * freq;
    double a = (double)ang;
    const double twopi = 6.283185307179586476925287;
    a -= floor(a / twopi) * twopi;
    float ar = (float)a;
    g_rtab[idx] = make_float2(cosf(ar), sinf(ar));
}

__global__ void rope_apply(float* __restrict__ q, float* __restrict__ k,
                           const int* __restrict__ pos)
{
    int idx = blockIdx.x * blockDim.x + threadIdx.x;   // MTOK*512
    if (idx >= MTOK * 512) return;
    int m = idx >> 9;
    int h = (idx >> 5) & 15;
    int i = idx & 31;
    float2 cs = g_rtab[pos[m] * 32 + i];
    size_t off = (size_t)m * DMOD + h * DK + 2 * i;
    float2 qv = *(float2*)(q + off);
    float2 kv = *(float2*)(k + off);
    float2 qo = make_float2(qv.x * cs.x - qv.y * cs.y, qv.x * cs.y + qv.y * cs.x);
    float2 ko = make_float2(kv.x * cs.x - kv.y * cs.y, kv.x * cs.y + kv.y * cs.x);
    *(float2*)(q + off) = qo;
    *(float2*)(k + off) = ko;
}

// ---------------------------------------------------------------------------
// Flash attention, causal, fp32 (verified in R1)
// ---------------------------------------------------------------------------
__global__ __launch_bounds__(256) void attn_kernel(const float* __restrict__ Q,
                                                   const float* __restrict__ K,
                                                   const float* __restrict__ V,
                                                   float* __restrict__ O)
{
    __shared__ float Qs[64][64];
    __shared__ float KVs[64][64];
    __shared__ float Ps[64][64];

    const int tid = threadIdx.x;
    const int ty = tid >> 4;
    const int tx = tid & 15;
    const int qt = blockIdx.x, h = blockIdx.y, b = blockIdx.z;
    const size_t base = ((size_t)b * SEQ) * DMOD + h * DK;

#pragma unroll
    for (int it = 0; it < 4; it++) {
        int idx = it * 256 + tid;
        int r = idx >> 4, f4 = idx & 15;
        *(float4*)&Qs[r][f4 * 4] =
            *(const float4*)(Q + base + (size_t)(qt * 64 + r) * DMOD + f4 * 4);
    }

    float m_run[4], l_run[4], acc[4][4];
#pragma unroll
    for (int i = 0; i < 4; i++) {
        m_run[i] = -1e30f; l_run[i] = 0.f;
#pragma unroll
        for (int j = 0; j < 4; j++) acc[i][j] = 0.f;
    }
    const float scale = 0.125f;

    for (int kt = 0; kt <= qt; kt++) {
        __syncthreads();
#pragma unroll
        for (int it = 0; it < 4; it++) {
            int idx = it * 256 + tid;
            int s = idx >> 4, f4 = idx & 15;
            float4 v = *(const float4*)(K + base + (size_t)(kt * 64 + s) * DMOD + f4 * 4);
            int sw = s ^ ((f4 & 7) << 2);
            int d0 = f4 * 4;
            KVs[d0 + 0][sw] = v.x; KVs[d0 + 1][sw] = v.y;
            KVs[d0 + 2][sw] = v.z; KVs[d0 + 3][sw] = v.w;
        }
        __syncthreads();

        float sreg[4][4];
#pragma unroll
        for (int i = 0; i < 4; i++)
#pragma unroll
            for (int j = 0; j < 4; j++) sreg[i][j] = 0.f;

#pragma unroll
        for (int d0 = 0; d0 < 64; d0 += 4) {
            float qa[4][4], kb[4][4];
            int colk = (tx * 4) ^ (((d0 >> 2) & 7) << 2);
#pragma unroll
            for (int i = 0; i < 4; i++)
                *(float4*)qa[i] = *(const float4*)&Qs[ty * 4 + i][d0];
#pragma unroll
            for (int c = 0; c < 4; c++)
                *(float4*)kb[c] = *(const float4*)&KVs[d0 + c][colk];
#pragma unroll
            for (int i = 0; i < 4; i++)
#pragma unroll
                for (int c = 0; c < 4; c++) {
                    float qv = qa[i][c];
#pragma unroll
                    for (int j = 0; j < 4; j++)
                        sreg[i][j] += qv * kb[c][j];
                }
        }

        if (kt == qt) {
#pragma unroll
            for (int i = 0; i < 4; i++)
#pragma unroll
                for (int j = 0; j < 4; j++) {
                    sreg[i][j] *= scale;
                    if (tx * 4 + j > ty * 4 + i) sreg[i][j] = -1e30f;
                }
        } else {
#pragma unroll
            for (int i = 0; i < 4; i++)
#pragma unroll
                for (int j = 0; j < 4; j++) sreg[i][j] *= scale;
        }

#pragma unroll
        for (int i = 0; i < 4; i++) {
            float mx = fmaxf(fmaxf(sreg[i][0], sreg[i][1]),
                             fmaxf(sreg[i][2], sreg[i][3]));
#pragma unroll
            for (int off = 8; off >= 1; off >>= 1)
                mx = fmaxf(mx, __shfl_xor_sync(0xffffffffu, mx, off));
            float mnew  = fmaxf(m_run[i], mx);
            float alpha = __expf(m_run[i] - mnew);
            float rs = 0.f;
#pragma unroll
            for (int j = 0; j < 4; j++) {
                float p = __expf(sreg[i][j] - mnew);
                sreg[i][j] = p;
                rs += p;
            }
#pragma unroll
            for (int off = 8; off >= 1; off >>= 1)
                rs += __shfl_xor_sync(0xffffffffu, rs, off);
            l_run[i] = l_run[i] * alpha + rs;
            m_run[i] = mnew;
#pragma unroll
            for (int j = 0; j < 4; j++) acc[i][j] *= alpha;
        }

#pragma unroll
        for (int i = 0; i < 4; i++)
            *(float4*)&Ps[ty * 4 + i][tx * 4] =
                make_float4(sreg[i][0], sreg[i][1], sreg[i][2], sreg[i][3]);
        __syncthreads();

#pragma unroll
        for (int it = 0; it < 4; it++) {
            int idx = it * 256 + tid;
            int r = idx >> 4, f4 = idx & 15;
            *(float4*)&KVs[r][f4 * 4] =
                *(const float4*)(V + base + (size_t)(kt * 64 + r) * DMOD + f4 * 4);
        }
        __syncthreads();

#pragma unroll
        for (int kk0 = 0; kk0 < 64; kk0 += 4) {
            float pa[4][4], vb[4][4];
#pragma unroll
            for (int i = 0; i < 4; i++)
                *(float4*)pa[i] = *(const float4*)&Ps[ty * 4 + i][kk0];
#pragma unroll
            for (int c = 0; c < 4; c++)
                *(float4*)vb[c] = *(const float4*)&KVs[kk0 + c][tx * 4];
#pragma unroll
            for (int i = 0; i < 4; i++)
#pragma unroll
                for (int c = 0; c < 4; c++) {
                    float pv = pa[i][c];
#pragma unroll
                    for (int j = 0; j < 4; j++)
                        acc[i][j] += pv * vb[c][j];
                }
        }
    }

#pragma unroll
    for (int i = 0; i < 4; i++) {
        float inv = 1.f / l_run[i];
        int row = qt * 64 + ty * 4 + i;
        float4 out = make_float4(acc[i][0] * inv, acc[i][1] * inv,
                                 acc[i][2] * inv, acc[i][3] * inv);
        *(float4*)(O + base + (size_t)row * DMOD + tx * 4) = out;
    }
}

// ---------------------------------------------------------------------------
extern "C" void kernel_launch(void* const* d_in, const int* in_sizes, int n_in,
                              void* d_out, int out_size)
{
    const float* x   = (const float*)d_in[0];
    const float* Wq  = (const float*)d_in[1];
    const float* Wk  = (const float*)d_in[2];
    const float* Wv  = (const float*)d_in[3];
    const float* Wo  = (const float*)d_in[4];
    const int*   pos = (const int*)d_in[5];
    float* out = (float*)d_out;

    float *q, *k, *v, *o;
    __half *xh, *oh, *wh;
    cudaGetSymbolAddress((void**)&q, g_q);
    cudaGetSymbolAddress((void**)&k, g_k);
    cudaGetSymbolAddress((void**)&v, g_v);
    cudaGetSymbolAddress((void**)&o, g_o);
    cudaGetSymbolAddress((void**)&xh, g_xh);
    cudaGetSymbolAddress((void**)&oh, g_oh);
    cudaGetSymbolAddress((void**)&wh, g_wh);

    const int WSZ = DMOD * DMOD;
    cvt_f16<<<(MTOK * DMOD / 4) / 256, 256>>>(x,  xh, MTOK * DMOD / 4);
    cvt_f16<<<(WSZ / 4) / 256, 256>>>(Wq, wh + 0 * WSZ, WSZ / 4);
    cvt_f16<<<(WSZ / 4) / 256, 256>>>(Wk, wh + 1 * WSZ, WSZ / 4);
    cvt_f16<<<(WSZ / 4) / 256, 256>>>(Wv, wh + 2 * WSZ, WSZ / 4);
    cvt_f16<<<(WSZ / 4) / 256, 256>>>(Wo, wh + 3 * WSZ, WSZ / 4);
    rope_table<<<(SEQ * 32) / 256, 256>>>();

    dim3 gg(DMOD / BN, MTOK / BM);
    hgemm<<<gg, 256>>>(xh, wh + 0 * WSZ, q, MTOK, DMOD, DMOD);
    hgemm<<<gg, 256>>>(xh, wh + 1 * WSZ, k, MTOK, DMOD, DMOD);
    hgemm<<<gg, 256>>>(xh, wh + 2 * WSZ, v, MTOK, DMOD, DMOD);
    rope_apply<<<(MTOK * 512) / 256, 256>>>(q, k, pos);
    attn_kernel<<<dim3(SEQ / 64, NH, 2), 256>>>(q, k, v, o);
    cvt_f16<<<(MTOK * DMOD / 4) / 256, 256>>>(o, oh, MTOK * DMOD / 4);
    hgemm<<<gg, 256>>>(oh, wh + 3 * WSZ, out, MTOK, DMOD, DMOD);
}

// round 4
// speedup vs baseline: 5.3083x; 2.7636x over previous
#include <cuda_runtime.h>
#include <cuda_fp16.h>
#include <cstdint>
#include <math.h>

#define MTOK 4096      // B*S tokens
#define DMOD 1024
#define SEQ  2048
#define NH   16
#define DK   64

// ---------------- scratch (no cudaMalloc allowed) ----------------
__device__ __half g_qh[MTOK * DMOD];
__device__ __half g_kh[MTOK * DMOD];
__device__ __half g_vh[MTOK * DMOD];
__device__ __half g_oh[MTOK * DMOD];
__device__ __half g_xh[MTOK * DMOD];
__device__ __half g_wh[4 * DMOD * DMOD];
__device__ float2 g_rtab[SEQ * 32];

// ---------------------------------------------------------------------------
__global__ void cvt_f16(const float* __restrict__ in, __half* __restrict__ out,
                        int n4)
{
    int i = blockIdx.x * blockDim.x + threadIdx.x;
    if (i >= n4) return;
    float4 v = ((const float4*)in)[i];
    ((__half2*)out)[i * 2]     = __floats2half2_rn(v.x, v.y);
    ((__half2*)out)[i * 2 + 1] = __floats2half2_rn(v.z, v.w);
}

// ---------------------------------------------------------------------------
// fp16 HMMA GEMM (verified R3): C[m][n] = sum_k A[m][k] * W[n][k]
// ---------------------------------------------------------------------------
#define BM 128
#define BN 128
#define BK 32
#define SA 40

template <typename OutT>
__global__ __launch_bounds__(256, 2) void hgemm(
    const __half* __restrict__ A, const __half* __restrict__ B,
    OutT* __restrict__ C, int M, int N, int K)
{
    __shared__ __align__(16) __half As[2][BM * SA];
    __shared__ __align__(16) __half Bs[2][BN * SA];

    const int tid = threadIdx.x;
    const int wid = tid >> 5, lane = tid & 31;
    const int wm = wid & 3, wn = wid >> 2;
    const int m0 = blockIdx.y * BM, n0 = blockIdx.x * BN;
    const int gid = lane >> 2, tg = lane & 3;
    const int ldrow = tid >> 2;
    const int ldseg = tid & 3;

    float acc[2][8][4];
#pragma unroll
    for (int i = 0; i < 2; i++)
#pragma unroll
        for (int j = 0; j < 8; j++)
#pragma unroll
            for (int r = 0; r < 4; r++) acc[i][j][r] = 0.f;

    auto issue_chunk = [&](int c, int buf) {
        const __half* ga = A + (size_t)m0 * K + (size_t)c * BK;
        const __half* gb = B + (size_t)n0 * K + (size_t)c * BK;
#pragma unroll
        for (int it = 0; it < 2; it++) {
            int row = it * 64 + ldrow;
            uint32_t sa = (uint32_t)__cvta_generic_to_shared(
                &As[buf][row * SA + ldseg * 8]);
            uint32_t sb = (uint32_t)__cvta_generic_to_shared(
                &Bs[buf][row * SA + ldseg * 8]);
            const __half* pa = ga + (size_t)row * K + ldseg * 8;
            const __half* pb = gb + (size_t)row * K + ldseg * 8;
            asm volatile("cp.async.cg.shared.global [%0], [%1], 16;"
                         :: "r"(sa), "l"(pa));
            asm volatile("cp.async.cg.shared.global [%0], [%1], 16;"
                         :: "r"(sb), "l"(pb));
        }
        asm volatile("cp.async.commit_group;");
    };

    const int KC = K / BK;
    issue_chunk(0, 0);

    const int a_row = wm * 32 + (lane & 15);
    const int a_col = (lane & 16) >> 1;
    const int b_row = (lane & 7) + ((lane & 16) >> 1);
    const int b_col = (lane & 8);

    for (int c = 0; c < KC; c++) {
        int buf = c & 1;
        if (c + 1 < KC) {
            issue_chunk(c + 1, buf ^ 1);
            asm volatile("cp.async.wait_group 1;");
        } else {
            asm volatile("cp.async.wait_group 0;");
        }
        __syncthreads();

#pragma unroll
        for (int ks = 0; ks < BK; ks += 16) {
            uint32_t af[2][4];
#pragma unroll
            for (int tm = 0; tm < 2; tm++) {
                uint32_t addr = (uint32_t)__cvta_generic_to_shared(
                    &As[buf][(a_row + tm * 16) * SA + ks + a_col]);
                asm volatile(
                    "ldmatrix.sync.aligned.m8n8.x4.shared.b16 {%0,%1,%2,%3}, [%4];"
                    : "=r"(af[tm][0]), "=r"(af[tm][1]),
                      "=r"(af[tm][2]), "=r"(af[tm][3]) : "r"(addr));
            }
            uint32_t bf[8][2];
#pragma unroll
            for (int np = 0; np < 4; np++) {
                uint32_t addr = (uint32_t)__cvta_generic_to_shared(
                    &Bs[buf][(wn * 64 + np * 16 + b_row) * SA + ks + b_col]);
                asm volatile(
                    "ldmatrix.sync.aligned.m8n8.x4.shared.b16 {%0,%1,%2,%3}, [%4];"
                    : "=r"(bf[np * 2][0]), "=r"(bf[np * 2][1]),
                      "=r"(bf[np * 2 + 1][0]), "=r"(bf[np * 2 + 1][1])
                    : "r"(addr));
            }
#pragma unroll
            for (int tm = 0; tm < 2; tm++)
#pragma unroll
                for (int tn = 0; tn < 8; tn++) {
                    asm volatile(
                        "mma.sync.aligned.m16n8k16.row.col.f32.f16.f16.f32 "
                        "{%0,%1,%2,%3}, {%4,%5,%6,%7}, {%8,%9}, {%0,%1,%2,%3};"
                        : "+f"(acc[tm][tn][0]), "+f"(acc[tm][tn][1]),
                          "+f"(acc[tm][tn][2]), "+f"(acc[tm][tn][3])
                        : "r"(af[tm][0]), "r"(af[tm][1]),
                          "r"(af[tm][2]), "r"(af[tm][3]),
                          "r"(bf[tn][0]), "r"(bf[tn][1]));
                }
        }
        __syncthreads();
    }

#pragma unroll
    for (int tm = 0; tm < 2; tm++) {
        int rbase = m0 + wm * 32 + tm * 16;
#pragma unroll
        for (int tn = 0; tn < 8; tn++) {
            int col = n0 + wn * 64 + tn * 8 + tg * 2;
            if constexpr (sizeof(OutT) == 4) {
                float* p0 = (float*)C + (size_t)(rbase + gid) * N + col;
                float* p1 = (float*)C + (size_t)(rbase + gid + 8) * N + col;
                *(float2*)p0 = make_float2(acc[tm][tn][0], acc[tm][tn][1]);
                *(float2*)p1 = make_float2(acc[tm][tn][2], acc[tm][tn][3]);
            } else {
                __half* p0 = (__half*)C + (size_t)(rbase + gid) * N + col;
                __half* p1 = (__half*)C + (size_t)(rbase + gid + 8) * N + col;
                *(__half2*)p0 = __floats2half2_rn(acc[tm][tn][0], acc[tm][tn][1]);
                *(__half2*)p1 = __floats2half2_rn(acc[tm][tn][2], acc[tm][tn][3]);
            }
        }
    }
}

// ---------------------------------------------------------------------------
// RoPE: FP64-accurate table once, then memory-bound fp16 apply
// ---------------------------------------------------------------------------
__global__ void rope_table()
{
    int idx = blockIdx.x * blockDim.x + threadIdx.x;
    if (idx >= SEQ * 32) return;
    int p = idx >> 5, i = idx & 31;
    float freq = (float)exp(-((double)(2 * i) / 64.0) * 9.210340371976184);
    float ang  = (float)p * freq;
    double a = (double)ang;
    const double twopi = 6.283185307179586476925287;
    a -= floor(a / twopi) * twopi;
    float ar = (float)a;
    g_rtab[idx] = make_float2(cosf(ar), sinf(ar));
}

__global__ void rope_apply(__half* __restrict__ q, __half* __restrict__ k,
                           const int* __restrict__ pos)
{
    int idx = blockIdx.x * blockDim.x + threadIdx.x;   // MTOK*512
    if (idx >= MTOK * 512) return;
    int m = idx >> 9;
    int h = (idx >> 5) & 15;
    int i = idx & 31;
    float2 cs = g_rtab[pos[m] * 32 + i];
    size_t off = (size_t)m * DMOD + h * DK + 2 * i;
    __half2 qv = *(__half2*)(q + off);
    __half2 kv = *(__half2*)(k + off);
    float qx = __low2float(qv), qy = __high2float(qv);
    float kx = __low2float(kv), ky = __high2float(kv);
    *(__half2*)(q + off) = __floats2half2_rn(qx * cs.x - qy * cs.y,
                                             qx * cs.y + qy * cs.x);
    *(__half2*)(k + off) = __floats2half2_rn(kx * cs.x - ky * cs.y,
                                             kx * cs.y + ky * cs.x);
}

// ---------------------------------------------------------------------------
// Tensor-core flash attention, causal, fp16 inputs / fp32 accum.
// CTA = (128 q-rows, head, batch). 8 warps, warp = 16 q-rows x 64-key tile.
// smem stride 72 halves -> conflict-free ldmatrix. K/V double-buffered.
// ---------------------------------------------------------------------------
#define SQH 72
#define ATT_SMEM ((128 * SQH + 4 * 64 * SQH) * 2)   // 55296 bytes

__global__ __launch_bounds__(256) void attn_mma(
    const __half* __restrict__ Q, const __half* __restrict__ K,
    const __half* __restrict__ V, __half* __restrict__ O)
{
    extern __shared__ __half sm[];
    __half* Qs = sm;                         // 128 x SQH
    __half* Kb = sm + 128 * SQH;             // 2 x 64 x SQH
    __half* Vb = sm + 128 * SQH + 2 * 64 * SQH;

    const int tid = threadIdx.x;
    const int w = tid >> 5, lane = tid & 31;
    const int gid = lane >> 2, tg = lane & 3;
    const int qt = blockIdx.x, h = blockIdx.y, b = blockIdx.z;
    const size_t base = ((size_t)b * SEQ) * DMOD + h * DK;
    const int qrow0 = qt * 128;

    const int lrow = tid >> 3, lseg = tid & 7;

    auto issue_kv = [&](int kt, int buf) {
#pragma unroll
        for (int it = 0; it < 2; it++) {
            int r = it * 32 + lrow;
            uint32_t dk_ = (uint32_t)__cvta_generic_to_shared(
                &Kb[buf * 64 * SQH + r * SQH + lseg * 8]);
            uint32_t dv_ = (uint32_t)__cvta_generic_to_shared(
                &Vb[buf * 64 * SQH + r * SQH + lseg * 8]);
            const __half* pk = K + base + (size_t)(kt * 64 + r) * DMOD + lseg * 8;
            const __half* pv = V + base + (size_t)(kt * 64 + r) * DMOD + lseg * 8;
            asm volatile("cp.async.cg.shared.global [%0], [%1], 16;"
                         :: "r"(dk_), "l"(pk));
            asm volatile("cp.async.cg.shared.global [%0], [%1], 16;"
                         :: "r"(dv_), "l"(pv));
        }
        asm volatile("cp.async.commit_group;");
    };

    // Q load + KV tile 0, one group
#pragma unroll
    for (int it = 0; it < 4; it++) {
        int r = it * 32 + lrow;
        uint32_t dq = (uint32_t)__cvta_generic_to_shared(
            &Qs[r * SQH + lseg * 8]);
        const __half* pq = Q + base + (size_t)(qrow0 + r) * DMOD + lseg * 8;
        asm volatile("cp.async.cg.shared.global [%0], [%1], 16;"
                     :: "r"(dq), "l"(pq));
    }
    issue_kv(0, 0);

    asm volatile("cp.async.wait_group 0;");
    __syncthreads();

    // Q fragments (register-resident for the whole kernel)
    uint32_t qf[4][4];
#pragma unroll
    for (int ks = 0; ks < 4; ks++) {
        uint32_t addr = (uint32_t)__cvta_generic_to_shared(
            &Qs[(w * 16 + (lane & 15)) * SQH + ks * 16 + ((lane >> 4) << 3)]);
        asm volatile(
            "ldmatrix.sync.aligned.m8n8.x4.shared.b16 {%0,%1,%2,%3}, [%4];"
            : "=r"(qf[ks][0]), "=r"(qf[ks][1]), "=r"(qf[ks][2]), "=r"(qf[ks][3])
            : "r"(addr));
    }

    float o[8][4];
    float m0 = -1e30f, m1 = -1e30f, l0 = 0.f, l1 = 0.f;
#pragma unroll
    for (int tn = 0; tn < 8; tn++)
#pragma unroll
        for (int r = 0; r < 4; r++) o[tn][r] = 0.f;

    const int brow = (lane & 7) + ((lane & 16) >> 1);
    const int bcol = (lane & 8);
    const int rabs0 = qrow0 + w * 16 + gid;
    const int ktmax = 2 * qt + 1;

    for (int kt = 0; kt <= ktmax; kt++) {
        int buf = kt & 1;
        if (kt) {
            asm volatile("cp.async.wait_group 0;");
            __syncthreads();
        }
        if (kt < ktmax) issue_kv(kt + 1, buf ^ 1);

        if (!(kt == 2 * qt + 1 && w < 4)) {     // skip fully-masked warp tiles
            const __half* Ks = Kb + buf * 64 * SQH;
            const __half* Vs = Vb + buf * 64 * SQH;

            // ---- S = Q K^T
            float s[8][4];
#pragma unroll
            for (int tn = 0; tn < 8; tn++)
#pragma unroll
                for (int r = 0; r < 4; r++) s[tn][r] = 0.f;

#pragma unroll
            for (int ks = 0; ks < 4; ks++) {
                uint32_t bf[8][2];
#pragma unroll
                for (int np = 0; np < 4; np++) {
                    uint32_t addr = (uint32_t)__cvta_generic_to_shared(
                        &Ks[(np * 16 + brow) * SQH + ks * 16 + bcol]);
                    asm volatile(
                        "ldmatrix.sync.aligned.m8n8.x4.shared.b16 {%0,%1,%2,%3}, [%4];"
                        : "=r"(bf[np * 2][0]), "=r"(bf[np * 2][1]),
                          "=r"(bf[np * 2 + 1][0]), "=r"(bf[np * 2 + 1][1])
                        : "r"(addr));
                }
#pragma unroll
                for (int tn = 0; tn < 8; tn++)
                    asm volatile(
                        "mma.sync.aligned.m16n8k16.row.col.f32.f16.f16.f32 "
                        "{%0,%1,%2,%3}, {%4,%5,%6,%7}, {%8,%9}, {%0,%1,%2,%3};"
                        : "+f"(s[tn][0]), "+f"(s[tn][1]),
                          "+f"(s[tn][2]), "+f"(s[tn][3])
                        : "r"(qf[ks][0]), "r"(qf[ks][1]),
                          "r"(qf[ks][2]), "r"(qf[ks][3]),
                          "r"(bf[tn][0]), "r"(bf[tn][1]));
            }

            // ---- scale + causal mask
            const float scale = 0.125f;
            bool need_mask = (kt >= 2 * qt);
#pragma unroll
            for (int tn = 0; tn < 8; tn++) {
                int cb = kt * 64 + tn * 8 + tg * 2;
                s[tn][0] *= scale; s[tn][1] *= scale;
                s[tn][2] *= scale; s[tn][3] *= scale;
                if (need_mask) {
                    if (cb     > rabs0)     s[tn][0] = -1e30f;
                    if (cb + 1 > rabs0)     s[tn][1] = -1e30f;
                    if (cb     > rabs0 + 8) s[tn][2] = -1e30f;
                    if (cb + 1 > rabs0 + 8) s[tn][3] = -1e30f;
                }
            }

            // ---- online softmax (rows gid, gid+8; reduce over quad)
            float mx0 = -1e30f, mx1 = -1e30f;
#pragma unroll
            for (int tn = 0; tn < 8; tn++) {
                mx0 = fmaxf(mx0, fmaxf(s[tn][0], s[tn][1]));
                mx1 = fmaxf(mx1, fmaxf(s[tn][2], s[tn][3]));
            }
            mx0 = fmaxf(mx0, __shfl_xor_sync(0xffffffffu, mx0, 1));
            mx0 = fmaxf(mx0, __shfl_xor_sync(0xffffffffu, mx0, 2));
            mx1 = fmaxf(mx1, __shfl_xor_sync(0xffffffffu, mx1, 1));
            mx1 = fmaxf(mx1, __shfl_xor_sync(0xffffffffu, mx1, 2));

            float mn0 = fmaxf(m0, mx0), mn1 = fmaxf(m1, mx1);
            float a0 = __expf(m0 - mn0), a1 = __expf(m1 - mn1);
            m0 = mn0; m1 = mn1;

            float rs0 = 0.f, rs1 = 0.f;
#pragma unroll
            for (int tn = 0; tn < 8; tn++) {
                s[tn][0] = __expf(s[tn][0] - mn0);
                s[tn][1] = __expf(s[tn][1] - mn0);
                s[tn][2] = __expf(s[tn][2] - mn1);
                s[tn][3] = __expf(s[tn][3] - mn1);
                rs0 += s[tn][0] + s[tn][1];
                rs1 += s[tn][2] + s[tn][3];
            }
            rs0 += __shfl_xor_sync(0xffffffffu, rs0, 1);
            rs0 += __shfl_xor_sync(0xffffffffu, rs0, 2);
            rs1 += __shfl_xor_sync(0xffffffffu, rs1, 1);
            rs1 += __shfl_xor_sync(0xffffffffu, rs1, 2);
            l0 = l0 * a0 + rs0;
            l1 = l1 * a1 + rs1;

#pragma unroll
            for (int tn = 0; tn < 8; tn++) {
                o[tn][0] *= a0; o[tn][1] *= a0;
                o[tn][2] *= a1; o[tn][3] *= a1;
            }

            // ---- O += P V  (P packed in regs; V via ldmatrix.trans)
#pragma unroll
            for (int ks = 0; ks < 4; ks++) {
                uint32_t pf[4];
                __half2 p0 = __floats2half2_rn(s[2 * ks][0], s[2 * ks][1]);
                __half2 p1 = __floats2half2_rn(s[2 * ks][2], s[2 * ks][3]);
                __half2 p2 = __floats2half2_rn(s[2 * ks + 1][0], s[2 * ks + 1][1]);
                __half2 p3 = __floats2half2_rn(s[2 * ks + 1][2], s[2 * ks + 1][3]);
                pf[0] = *(uint32_t*)&p0; pf[1] = *(uint32_t*)&p1;
                pf[2] = *(uint32_t*)&p2; pf[3] = *(uint32_t*)&p3;

                uint32_t vb[8][2];
#pragma unroll
                for (int np = 0; np < 4; np++) {
                    uint32_t addr = (uint32_t)__cvta_generic_to_shared(
                        &Vs[(ks * 16 + (lane & 15)) * SQH + np * 16
                            + ((lane & 16) >> 1)]);
                    asm volatile(
                        "ldmatrix.sync.aligned.m8n8.x4.trans.shared.b16 "
                        "{%0,%1,%2,%3}, [%4];"
                        : "=r"(vb[np * 2][0]), "=r"(vb[np * 2][1]),
                          "=r"(vb[np * 2 + 1][0]), "=r"(vb[np * 2 + 1][1])
                        : "r"(addr));
                }
#pragma unroll
                for (int tn = 0; tn < 8; tn++)
                    asm volatile(
                        "mma.sync.aligned.m16n8k16.row.col.f32.f16.f16.f32 "
                        "{%0,%1,%2,%3}, {%4,%5,%6,%7}, {%8,%9}, {%0,%1,%2,%3};"
                        : "+f"(o[tn][0]), "+f"(o[tn][1]),
                          "+f"(o[tn][2]), "+f"(o[tn][3])
                        : "r"(pf[0]), "r"(pf[1]), "r"(pf[2]), "r"(pf[3]),
                          "r"(vb[tn][0]), "r"(vb[tn][1]));
            }
        }
    }

    // ---- epilogue: normalize, write fp16
    float i0 = 1.f / l0, i1 = 1.f / l1;
    if (2 * qt + 1 == ktmax && w < 4 && l0 == 0.f) { i0 = 0.f; i1 = 0.f; } // unreachable guard
#pragma unroll
    for (int tn = 0; tn < 8; tn++) {
        size_t r0 = base + (size_t)(qrow0 + w * 16 + gid) * DMOD + tn * 8 + tg * 2;
        size_t r1 = r0 + 8 * DMOD;
        *(__half2*)(O + r0) = __floats2half2_rn(o[tn][0] * i0, o[tn][1] * i0);
        *(__half2*)(O + r1) = __floats2half2_rn(o[tn][2] * i1, o[tn][3] * i1);
    }
}

// ---------------------------------------------------------------------------
extern "C" void kernel_launch(void* const* d_in, const int* in_sizes, int n_in,
                              void* d_out, int out_size)
{
    const float* x   = (const float*)d_in[0];
    const float* Wq  = (const float*)d_in[1];
    const float* Wk  = (const float*)d_in[2];
    const float* Wv  = (const float*)d_in[3];
    const float* Wo  = (const float*)d_in[4];
    const int*   pos = (const int*)d_in[5];
    float* out = (float*)d_out;

    __half *qh, *kh, *vh, *oh, *xh, *wh;
    cudaGetSymbolAddress((void**)&qh, g_qh);
    cudaGetSymbolAddress((void**)&kh, g_kh);
    cudaGetSymbolAddress((void**)&vh, g_vh);
    cudaGetSymbolAddress((void**)&oh, g_oh);
    cudaGetSymbolAddress((void**)&xh, g_xh);
    cudaGetSymbolAddress((void**)&wh, g_wh);

    cudaFuncSetAttribute(attn_mma, cudaFuncAttributeMaxDynamicSharedMemorySize,
                         ATT_SMEM);

    const int WSZ = DMOD * DMOD;
    cvt_f16<<<(MTOK * DMOD / 4) / 256, 256>>>(x,  xh, MTOK * DMOD / 4);
    cvt_f16<<<(WSZ / 4) / 256, 256>>>(Wq, wh + 0 * WSZ, WSZ / 4);
    cvt_f16<<<(WSZ / 4) / 256, 256>>>(Wk, wh + 1 * WSZ, WSZ / 4);
    cvt_f16<<<(WSZ / 4) / 256, 256>>>(Wv, wh + 2 * WSZ, WSZ / 4);
    cvt_f16<<<(WSZ / 4) / 256, 256>>>(Wo, wh + 3 * WSZ, WSZ / 4);
    rope_table<<<(SEQ * 32) / 256, 256>>>();

    dim3 gg(DMOD / BN, MTOK / BM);
    hgemm<__half><<<gg, 256>>>(xh, wh + 0 * WSZ, qh, MTOK, DMOD, DMOD);
    hgemm<__half><<<gg, 256>>>(xh, wh + 1 * WSZ, kh, MTOK, DMOD, DMOD);
    hgemm<__half><<<gg, 256>>>(xh, wh + 2 * WSZ, vh, MTOK, DMOD, DMOD);
    rope_apply<<<(MTOK * 512) / 256, 256>>>(qh, kh, pos);
    attn_mma<<<dim3(SEQ / 128, NH, 2), 256, ATT_SMEM>>>(qh, kh, vh, oh);
    hgemm<float><<<gg, 256>>>(oh, wh + 3 * WSZ, out, MTOK, DMOD, DMOD);
}

// round 5
// speedup vs baseline: 6.0160x; 1.1333x over previous
#include <cuda_runtime.h>
#include <cuda_fp16.h>
#include <cstdint>
#include <math.h>

#define MTOK 4096      // B*S tokens
#define DMOD 1024
#define SEQ  2048
#define NH   16
#define DK   64
#define NQKV 3072      // fused q|k|v width

// ---------------- scratch (no cudaMalloc allowed) ----------------
__device__ __half g_xh[MTOK * DMOD];
__device__ __half g_qkv[MTOK * NQKV];
__device__ __half g_oh[MTOK * DMOD];
__device__ __half g_wqkv[NQKV * DMOD];   // rows: [Wq(1024) | Wk(1024) | Wv(1024)]
__device__ __half g_wo[DMOD * DMOD];
__device__ float2 g_rtab[SEQ * 32];

// ---------------------------------------------------------------------------
__global__ void cvt_f16(const float* __restrict__ in, __half* __restrict__ out,
                        int n4)
{
    int i = blockIdx.x * blockDim.x + threadIdx.x;
    if (i >= n4) return;
    float4 v = ((const float4*)in)[i];
    ((__half2*)out)[i * 2]     = __floats2half2_rn(v.x, v.y);
    ((__half2*)out)[i * 2 + 1] = __floats2half2_rn(v.z, v.w);
}

// one launch converts all 4 weight matrices (1M floats each)
__global__ void cvt_w4(const float* __restrict__ w0, const float* __restrict__ w1,
                       const float* __restrict__ w2, const float* __restrict__ w3)
{
    int idx = blockIdx.x * blockDim.x + threadIdx.x;   // 0 .. 4*2^18-1 (float4)
    int sel = idx >> 18;
    int off = idx & 0x3FFFF;
    const float* src = sel == 0 ? w0 : sel == 1 ? w1 : sel == 2 ? w2 : w3;
    __half* dst = (sel < 3) ? g_wqkv + (size_t)sel * DMOD * DMOD : g_wo;
    float4 v = ((const float4*)src)[off];
    ((__half2*)dst)[off * 2]     = __floats2half2_rn(v.x, v.y);
    ((__half2*)dst)[off * 2 + 1] = __floats2half2_rn(v.z, v.w);
}

// ---------------------------------------------------------------------------
// RoPE table: FP64-accurate once per (pos, i)
// ---------------------------------------------------------------------------
__global__ void rope_table()
{
    int idx = blockIdx.x * blockDim.x + threadIdx.x;
    if (idx >= SEQ * 32) return;
    int p = idx >> 5, i = idx & 31;
    float freq = (float)exp(-((double)(2 * i) / 64.0) * 9.210340371976184);
    float ang  = (float)p * freq;
    double a = (double)ang;
    const double twopi = 6.283185307179586476925287;
    a -= floor(a / twopi) * twopi;
    float ar = (float)a;
    g_rtab[idx] = make_float2(cosf(ar), sinf(ar));
}

// ---------------------------------------------------------------------------
// fp16 HMMA GEMM (R3/R4-verified core), 3-stage cp.async pipeline,
// optional fused RoPE in the epilogue (columns < 2048 = q|k sections).
// C[m][n] = sum_k A[m][k] * B[n][k]
// ---------------------------------------------------------------------------
#define BM 128
#define BN 128
#define BK 32
#define SA 40
#define STAGE_E (BM * SA)                  // halves per stage per operand
#define HG_SMEM (3 * 2 * STAGE_E * 2)      // 61440 bytes

template <typename OutT, bool DO_ROPE>
__global__ __launch_bounds__(256, 2) void hgemm(
    const __half* __restrict__ A, const __half* __restrict__ B,
    OutT* __restrict__ C, const int* __restrict__ pos,
    int M, int N, int K)
{
    extern __shared__ __half hsm[];
    __half* As = hsm;                      // 3 stages
    __half* Bs = hsm + 3 * STAGE_E;

    const int tid = threadIdx.x;
    const int wid = tid >> 5, lane = tid & 31;
    const int wm = wid & 3, wn = wid >> 2;
    const int m0 = blockIdx.y * BM, n0 = blockIdx.x * BN;
    const int gid = lane >> 2, tg = lane & 3;
    const int ldrow = tid >> 2;
    const int ldseg = tid & 3;

    float acc[2][8][4];
#pragma unroll
    for (int i = 0; i < 2; i++)
#pragma unroll
        for (int j = 0; j < 8; j++)
#pragma unroll
            for (int r = 0; r < 4; r++) acc[i][j][r] = 0.f;

    auto issue_chunk = [&](int c, int buf) {
        const __half* ga = A + (size_t)m0 * K + (size_t)c * BK;
        const __half* gb = B + (size_t)n0 * K + (size_t)c * BK;
        __half* sa_base = As + buf * STAGE_E;
        __half* sb_base = Bs + buf * STAGE_E;
#pragma unroll
        for (int it = 0; it < 2; it++) {
            int row = it * 64 + ldrow;
            uint32_t sa = (uint32_t)__cvta_generic_to_shared(
                &sa_base[row * SA + ldseg * 8]);
            uint32_t sb = (uint32_t)__cvta_generic_to_shared(
                &sb_base[row * SA + ldseg * 8]);
            const __half* pa = ga + (size_t)row * K + ldseg * 8;
            const __half* pb = gb + (size_t)row * K + ldseg * 8;
            asm volatile("cp.async.cg.shared.global [%0], [%1], 16;"
                         :: "r"(sa), "l"(pa));
            asm volatile("cp.async.cg.shared.global [%0], [%1], 16;"
                         :: "r"(sb), "l"(pb));
        }
        asm volatile("cp.async.commit_group;");
    };

    const int KC = K / BK;                 // >= 3 always here
    issue_chunk(0, 0);
    issue_chunk(1, 1);

    const int a_row = wm * 32 + (lane & 15);
    const int a_col = (lane & 16) >> 1;
    const int b_row = (lane & 7) + ((lane & 16) >> 1);
    const int b_col = (lane & 8);

    for (int c = 0; c < KC; c++) {
        if (c + 1 < KC) asm volatile("cp.async.wait_group 1;");
        else            asm volatile("cp.async.wait_group 0;");
        __syncthreads();
        if (c + 2 < KC) issue_chunk(c + 2, (c + 2) % 3);

        const __half* sa_base = As + (c % 3) * STAGE_E;
        const __half* sb_base = Bs + (c % 3) * STAGE_E;

#pragma unroll
        for (int ks = 0; ks < BK; ks += 16) {
            uint32_t af[2][4];
#pragma unroll
            for (int tm = 0; tm < 2; tm++) {
                uint32_t addr = (uint32_t)__cvta_generic_to_shared(
                    &sa_base[(a_row + tm * 16) * SA + ks + a_col]);
                asm volatile(
                    "ldmatrix.sync.aligned.m8n8.x4.shared.b16 {%0,%1,%2,%3}, [%4];"
                    : "=r"(af[tm][0]), "=r"(af[tm][1]),
                      "=r"(af[tm][2]), "=r"(af[tm][3]) : "r"(addr));
            }
            uint32_t bf[8][2];
#pragma unroll
            for (int np = 0; np < 4; np++) {
                uint32_t addr = (uint32_t)__cvta_generic_to_shared(
                    &sb_base[(wn * 64 + np * 16 + b_row) * SA + ks + b_col]);
                asm volatile(
                    "ldmatrix.sync.aligned.m8n8.x4.shared.b16 {%0,%1,%2,%3}, [%4];"
                    : "=r"(bf[np * 2][0]), "=r"(bf[np * 2][1]),
                      "=r"(bf[np * 2 + 1][0]), "=r"(bf[np * 2 + 1][1])
                    : "r"(addr));
            }
#pragma unroll
            for (int tm = 0; tm < 2; tm++)
#pragma unroll
                for (int tn = 0; tn < 8; tn++) {
                    asm volatile(
                        "mma.sync.aligned.m16n8k16.row.col.f32.f16.f16.f32 "
                        "{%0,%1,%2,%3}, {%4,%5,%6,%7}, {%8,%9}, {%0,%1,%2,%3};"
                        : "+f"(acc[tm][tn][0]), "+f"(acc[tm][tn][1]),
                          "+f"(acc[tm][tn][2]), "+f"(acc[tm][tn][3])
                        : "r"(af[tm][0]), "r"(af[tm][1]),
                          "r"(af[tm][2]), "r"(af[tm][3]),
                          "r"(bf[tn][0]), "r"(bf[tn][1]));
                }
        }
        __syncthreads();
    }

    // epilogue (+ fused RoPE for q|k sections)
    const bool do_rot = DO_ROPE && (n0 < 2048);
#pragma unroll
    for (int tm = 0; tm < 2; tm++) {
        int rbase = m0 + wm * 32 + tm * 16;
        int r0 = rbase + gid, r1 = rbase + gid + 8;
        int p0 = 0, p1 = 0;
        if (do_rot) { p0 = pos[r0]; p1 = pos[r1]; }
#pragma unroll
        for (int tn = 0; tn < 8; tn++) {
            int col = n0 + wn * 64 + tn * 8 + tg * 2;
            float v00 = acc[tm][tn][0], v01 = acc[tm][tn][1];
            float v10 = acc[tm][tn][2], v11 = acc[tm][tn][3];
            if (do_rot) {
                int i = (col & 63) >> 1;
                float2 c0 = g_rtab[p0 * 32 + i];
                float2 c1 = g_rtab[p1 * 32 + i];
                float t0 = v00 * c0.x - v01 * c0.y;
                v01 = v00 * c0.y + v01 * c0.x; v00 = t0;
                float t1 = v10 * c1.x - v11 * c1.y;
                v11 = v10 * c1.y + v11 * c1.x; v10 = t1;
            }
            if constexpr (sizeof(OutT) == 4) {
                float* q0 = (float*)C + (size_t)r0 * N + col;
                float* q1 = (float*)C + (size_t)r1 * N + col;
                *(float2*)q0 = make_float2(v00, v01);
                *(float2*)q1 = make_float2(v10, v11);
            } else {
                __half* q0 = (__half*)C + (size_t)r0 * N + col;
                __half* q1 = (__half*)C + (size_t)r1 * N + col;
                *(__half2*)q0 = __floats2half2_rn(v00, v01);
                *(__half2*)q1 = __floats2half2_rn(v10, v11);
            }
        }
    }
}

// ---------------------------------------------------------------------------
// Tensor-core flash attention, causal (R4-verified), reading the fused
// [tok][3072] q|k|v layout (stride NQKV), writing O [tok][1024] fp16.
// ---------------------------------------------------------------------------
#define SQH 72
#define ATT_SMEM ((128 * SQH + 4 * 64 * SQH) * 2)   // 55296 bytes

__global__ __launch_bounds__(256) void attn_mma(
    const __half* __restrict__ Q, const __half* __restrict__ K,
    const __half* __restrict__ V, __half* __restrict__ O)
{
    extern __shared__ __half sm[];
    __half* Qs = sm;
    __half* Kb = sm + 128 * SQH;
    __half* Vb = sm + 128 * SQH + 2 * 64 * SQH;

    const int tid = threadIdx.x;
    const int w = tid >> 5, lane = tid & 31;
    const int gid = lane >> 2, tg = lane & 3;
    const int qt = blockIdx.x, h = blockIdx.y, b = blockIdx.z;
    const size_t base  = ((size_t)b * SEQ) * NQKV + h * DK;   // q/k/v (strided)
    const size_t baseO = ((size_t)b * SEQ) * DMOD + h * DK;
    const int qrow0 = qt * 128;

    const int lrow = tid >> 3, lseg = tid & 7;

    auto issue_kv = [&](int kt, int buf) {
#pragma unroll
        for (int it = 0; it < 2; it++) {
            int r = it * 32 + lrow;
            uint32_t dk_ = (uint32_t)__cvta_generic_to_shared(
                &Kb[buf * 64 * SQH + r * SQH + lseg * 8]);
            uint32_t dv_ = (uint32_t)__cvta_generic_to_shared(
                &Vb[buf * 64 * SQH + r * SQH + lseg * 8]);
            const __half* pk = K + base + (size_t)(kt * 64 + r) * NQKV + lseg * 8;
            const __half* pv = V + base + (size_t)(kt * 64 + r) * NQKV + lseg * 8;
            asm volatile("cp.async.cg.shared.global [%0], [%1], 16;"
                         :: "r"(dk_), "l"(pk));
            asm volatile("cp.async.cg.shared.global [%0], [%1], 16;"
                         :: "r"(dv_), "l"(pv));
        }
        asm volatile("cp.async.commit_group;");
    };

#pragma unroll
    for (int it = 0; it < 4; it++) {
        int r = it * 32 + lrow;
        uint32_t dq = (uint32_t)__cvta_generic_to_shared(
            &Qs[r * SQH + lseg * 8]);
        const __half* pq = Q + base + (size_t)(qrow0 + r) * NQKV + lseg * 8;
        asm volatile("cp.async.cg.shared.global [%0], [%1], 16;"
                     :: "r"(dq), "l"(pq));
    }
    issue_kv(0, 0);

    asm volatile("cp.async.wait_group 0;");
    __syncthreads();

    uint32_t qf[4][4];
#pragma unroll
    for (int ks = 0; ks < 4; ks++) {
        uint32_t addr = (uint32_t)__cvta_generic_to_shared(
            &Qs[(w * 16 + (lane & 15)) * SQH + ks * 16 + ((lane >> 4) << 3)]);
        asm volatile(
            "ldmatrix.sync.aligned.m8n8.x4.shared.b16 {%0,%1,%2,%3}, [%4];"
            : "=r"(qf[ks][0]), "=r"(qf[ks][1]), "=r"(qf[ks][2]), "=r"(qf[ks][3])
            : "r"(addr));
    }

    float o[8][4];
    float m0 = -1e30f, m1 = -1e30f, l0 = 0.f, l1 = 0.f;
#pragma unroll
    for (int tn = 0; tn < 8; tn++)
#pragma unroll
        for (int r = 0; r < 4; r++) o[tn][r] = 0.f;

    const int brow = (lane & 7) + ((lane & 16) >> 1);
    const int bcol = (lane & 8);
    const int rabs0 = qrow0 + w * 16 + gid;
    const int ktmax = 2 * qt + 1;

    for (int kt = 0; kt <= ktmax; kt++) {
        int buf = kt & 1;
        if (kt) {
            asm volatile("cp.async.wait_group 0;");
            __syncthreads();
        }
        if (kt < ktmax) issue_kv(kt + 1, buf ^ 1);

        if (!(kt == 2 * qt + 1 && w < 4)) {
            const __half* Ks = Kb + buf * 64 * SQH;
            const __half* Vs = Vb + buf * 64 * SQH;

            float s[8][4];
#pragma unroll
            for (int tn = 0; tn < 8; tn++)
#pragma unroll
                for (int r = 0; r < 4; r++) s[tn][r] = 0.f;

#pragma unroll
            for (int ks = 0; ks < 4; ks++) {
                uint32_t bf[8][2];
#pragma unroll
                for (int np = 0; np < 4; np++) {
                    uint32_t addr = (uint32_t)__cvta_generic_to_shared(
                        &Ks[(np * 16 + brow) * SQH + ks * 16 + bcol]);
                    asm volatile(
                        "ldmatrix.sync.aligned.m8n8.x4.shared.b16 {%0,%1,%2,%3}, [%4];"
                        : "=r"(bf[np * 2][0]), "=r"(bf[np * 2][1]),
                          "=r"(bf[np * 2 + 1][0]), "=r"(bf[np * 2 + 1][1])
                        : "r"(addr));
                }
#pragma unroll
                for (int tn = 0; tn < 8; tn++)
                    asm volatile(
                        "mma.sync.aligned.m16n8k16.row.col.f32.f16.f16.f32 "
                        "{%0,%1,%2,%3}, {%4,%5,%6,%7}, {%8,%9}, {%0,%1,%2,%3};"
                        : "+f"(s[tn][0]), "+f"(s[tn][1]),
                          "+f"(s[tn][2]), "+f"(s[tn][3])
                        : "r"(qf[ks][0]), "r"(qf[ks][1]),
                          "r"(qf[ks][2]), "r"(qf[ks][3]),
                          "r"(bf[tn][0]), "r"(bf[tn][1]));
            }

            const float scale = 0.125f;
            bool need_mask = (kt >= 2 * qt);
#pragma unroll
            for (int tn = 0; tn < 8; tn++) {
                int cb = kt * 64 + tn * 8 + tg * 2;
                s[tn][0] *= scale; s[tn][1] *= scale;
                s[tn][2] *= scale; s[tn][3] *= scale;
                if (need_mask) {
                    if (cb     > rabs0)     s[tn][0] = -1e30f;
                    if (cb + 1 > rabs0)     s[tn][1] = -1e30f;
                    if (cb     > rabs0 + 8) s[tn][2] = -1e30f;
                    if (cb + 1 > rabs0 + 8) s[tn][3] = -1e30f;
                }
            }

            float mx0 = -1e30f, mx1 = -1e30f;
#pragma unroll
            for (int tn = 0; tn < 8; tn++) {
                mx0 = fmaxf(mx0, fmaxf(s[tn][0], s[tn][1]));
                mx1 = fmaxf(mx1, fmaxf(s[tn][2], s[tn][3]));
            }
            mx0 = fmaxf(mx0, __shfl_xor_sync(0xffffffffu, mx0, 1));
            mx0 = fmaxf(mx0, __shfl_xor_sync(0xffffffffu, mx0, 2));
            mx1 = fmaxf(mx1, __shfl_xor_sync(0xffffffffu, mx1, 1));
            mx1 = fmaxf(mx1, __shfl_xor_sync(0xffffffffu, mx1, 2));

            float mn0 = fmaxf(m0, mx0), mn1 = fmaxf(m1, mx1);
            float a0 = __expf(m0 - mn0), a1 = __expf(m1 - mn1);
            m0 = mn0; m1 = mn1;

            float rs0 = 0.f, rs1 = 0.f;
#pragma unroll
            for (int tn = 0; tn < 8; tn++) {
                s[tn][0] = __expf(s[tn][0] - mn0);
                s[tn][1] = __expf(s[tn][1] - mn0);
                s[tn][2] = __expf(s[tn][2] - mn1);
                s[tn][3] = __expf(s[tn][3] - mn1);
                rs0 += s[tn][0] + s[tn][1];
                rs1 += s[tn][2] + s[tn][3];
            }
            rs0 += __shfl_xor_sync(0xffffffffu, rs0, 1);
            rs0 += __shfl_xor_sync(0xffffffffu, rs0, 2);
            rs1 += __shfl_xor_sync(0xffffffffu, rs1, 1);
            rs1 += __shfl_xor_sync(0xffffffffu, rs1, 2);
            l0 = l0 * a0 + rs0;
            l1 = l1 * a1 + rs1;

#pragma unroll
            for (int tn = 0; tn < 8; tn++) {
                o[tn][0] *= a0; o[tn][1] *= a0;
                o[tn][2] *= a1; o[tn][3] *= a1;
            }

#pragma unroll
            for (int ks = 0; ks < 4; ks++) {
                uint32_t pf[4];
                __half2 p0 = __floats2half2_rn(s[2 * ks][0], s[2 * ks][1]);
                __half2 p1 = __floats2half2_rn(s[2 * ks][2], s[2 * ks][3]);
                __half2 p2 = __floats2half2_rn(s[2 * ks + 1][0], s[2 * ks + 1][1]);
                __half2 p3 = __floats2half2_rn(s[2 * ks + 1][2], s[2 * ks + 1][3]);
                pf[0] = *(uint32_t*)&p0; pf[1] = *(uint32_t*)&p1;
                pf[2] = *(uint32_t*)&p2; pf[3] = *(uint32_t*)&p3;

                uint32_t vb[8][2];
#pragma unroll
                for (int np = 0; np < 4; np++) {
                    uint32_t addr = (uint32_t)__cvta_generic_to_shared(
                        &Vs[(ks * 16 + (lane & 15)) * SQH + np * 16
                            + ((lane & 16) >> 1)]);
                    asm volatile(
                        "ldmatrix.sync.aligned.m8n8.x4.trans.shared.b16 "
                        "{%0,%1,%2,%3}, [%4];"
                        : "=r"(vb[np * 2][0]), "=r"(vb[np * 2][1]),
                          "=r"(vb[np * 2 + 1][0]), "=r"(vb[np * 2 + 1][1])
                        : "r"(addr));
                }
#pragma unroll
                for (int tn = 0; tn < 8; tn++)
                    asm volatile(
                        "mma.sync.aligned.m16n8k16.row.col.f32.f16.f16.f32 "
                        "{%0,%1,%2,%3}, {%4,%5,%6,%7}, {%8,%9}, {%0,%1,%2,%3};"
                        : "+f"(o[tn][0]), "+f"(o[tn][1]),
                          "+f"(o[tn][2]), "+f"(o[tn][3])
                        : "r"(pf[0]), "r"(pf[1]), "r"(pf[2]), "r"(pf[3]),
                          "r"(vb[tn][0]), "r"(vb[tn][1]));
            }
        }
    }

    float i0 = 1.f / l0, i1 = 1.f / l1;
#pragma unroll
    for (int tn = 0; tn < 8; tn++) {
        size_t r0 = baseO + (size_t)(qrow0 + w * 16 + gid) * DMOD + tn * 8 + tg * 2;
        size_t r1 = r0 + 8 * DMOD;
        *(__half2*)(O + r0) = __floats2half2_rn(o[tn][0] * i0, o[tn][1] * i0);
        *(__half2*)(O + r1) = __floats2half2_rn(o[tn][2] * i1, o[tn][3] * i1);
    }
}

// ---------------------------------------------------------------------------
extern "C" void kernel_launch(void* const* d_in, const int* in_sizes, int n_in,
                              void* d_out, int out_size)
{
    const float* x   = (const float*)d_in[0];
    const float* Wq  = (const float*)d_in[1];
    const float* Wk  = (const float*)d_in[2];
    const float* Wv  = (const float*)d_in[3];
    const float* Wo  = (const float*)d_in[4];
    const int*   pos = (const int*)d_in[5];
    float* out = (float*)d_out;

    __half *xh, *qkv, *oh, *wqkv, *wo;
    cudaGetSymbolAddress((void**)&xh,   g_xh);
    cudaGetSymbolAddress((void**)&qkv,  g_qkv);
    cudaGetSymbolAddress((void**)&oh,   g_oh);
    cudaGetSymbolAddress((void**)&wqkv, g_wqkv);
    cudaGetSymbolAddress((void**)&wo,   g_wo);

    cudaFuncSetAttribute(hgemm<__half, true>,
                         cudaFuncAttributeMaxDynamicSharedMemorySize, HG_SMEM);
    cudaFuncSetAttribute(hgemm<float, false>,
                         cudaFuncAttributeMaxDynamicSharedMemorySize, HG_SMEM);
    cudaFuncSetAttribute(attn_mma,
                         cudaFuncAttributeMaxDynamicSharedMemorySize, ATT_SMEM);

    cvt_f16<<<(MTOK * DMOD / 4) / 256, 256>>>(x, xh, MTOK * DMOD / 4);
    cvt_w4<<<(4 * DMOD * DMOD / 4) / 256, 256>>>(Wq, Wk, Wv, Wo);
    rope_table<<<(SEQ * 32) / 256, 256>>>();

    // fused QKV projection + RoPE-in-epilogue
    hgemm<__half, true><<<dim3(NQKV / BN, MTOK / BM), 256, HG_SMEM>>>(
        xh, wqkv, qkv, pos, MTOK, NQKV, DMOD);

    attn_mma<<<dim3(SEQ / 128, NH, 2), 256, ATT_SMEM>>>(
        qkv, qkv + 1024, qkv + 2048, oh);

    hgemm<float, false><<<dim3(DMOD / BN, MTOK / BM), 256, HG_SMEM>>>(
        oh, wo, out, nullptr, MTOK, DMOD, DMOD);
}